// round 8
// baseline (speedup 1.0000x reference)
#include <cuda_runtime.h>
#include <mma.h>
#include <math.h>

using namespace nvcuda;

#define BB 4
#define LL 2048
#define KK 48
#define HH 128
#define FFD 512

// converted (tf32-rounded) weight offsets in g_cw
#define CW1   0
#define CW2   49152
#define CW3   65536
#define CW11  81920
#define CW12  131072
#define CW13  147456
#define CWIN  163840
#define CWOUT 229376
#define CWTOT 294912

__device__ float g_cw[CWTOT];
__device__ float g_v1[BB*LL*HH];   // h_V after node update + LN1
__device__ float g_v2[BB*LL*HH];   // h_V after FFN + LN2 + mask

__device__ __forceinline__ float tf32r(float x){
    float r;
    asm("{\n .reg .b32 t;\n cvt.rna.tf32.f32 t, %1;\n mov.b32 %0, t;\n}"
        : "=f"(r) : "f"(x));
    return r;
}
__device__ __forceinline__ float gelu_f(float x){
    return 0.5f * x * (1.0f + erff(x * 0.7071067811865476f));
}

// ---------------------------------------------------------------------------
// Weight conversion: fp32 -> tf32-rounded fp32 (RNA), into g_cw
// ---------------------------------------------------------------------------
__global__ void cvt_weights(const float* __restrict__ w1, const float* __restrict__ w2,
                            const float* __restrict__ w3, const float* __restrict__ w11,
                            const float* __restrict__ w12, const float* __restrict__ w13,
                            const float* __restrict__ win, const float* __restrict__ wout){
    int i = blockIdx.x * blockDim.x + threadIdx.x;
    if (i >= CWTOT) return;
    float v;
    if      (i < CW2)   v = w1[i - CW1];
    else if (i < CW3)   v = w2[i - CW2];
    else if (i < CW11)  v = w3[i - CW3];
    else if (i < CW12)  v = w11[i - CW11];
    else if (i < CW13)  v = w12[i - CW12];
    else if (i < CWIN)  v = w13[i - CW13];
    else if (i < CWOUT) v = win[i - CWIN];
    else                v = wout[i - CWOUT];
    g_cw[i] = tf32r(v);
}

// ---------------------------------------------------------------------------
// Warp-level GEMM: C[48x128] += A[48xK] * B[KxN=128]
// A: smem row-major (lda), B: global "W^T" = W row-major viewed col-major (ldb=K)
// warp `n0/16` owns a 16-wide column strip, 3 row tiles. NK = K/8 k-steps.
// ---------------------------------------------------------------------------
template<int NK>
__device__ __forceinline__ void warp_gemm48(const float* __restrict__ As, int lda,
                                            const float* __restrict__ Bg, int ldb,
                                            float* __restrict__ Out, int ldo, int n0){
    wmma::fragment<wmma::accumulator,16,16,8,float> c[3];
#pragma unroll
    for (int t = 0; t < 3; t++) wmma::fill_fragment(c[t], 0.0f);
    wmma::fragment<wmma::matrix_b,16,16,8,wmma::precision::tf32,wmma::col_major> bf[2];
    const float* Bp = Bg + (size_t)n0 * ldb;
    wmma::load_matrix_sync(bf[0], Bp, ldb);
#pragma unroll 4
    for (int ks = 0; ks < NK; ks++){
        if (ks + 1 < NK)
            wmma::load_matrix_sync(bf[(ks + 1) & 1], Bp + (ks + 1) * 8, ldb);
#pragma unroll
        for (int t = 0; t < 3; t++){
            wmma::fragment<wmma::matrix_a,16,16,8,wmma::precision::tf32,wmma::row_major> af;
            wmma::load_matrix_sync(af, As + t * 16 * lda + ks * 8, lda);
            wmma::mma_sync(c[t], af, bf[ks & 1], c[t]);
        }
    }
#pragma unroll
    for (int t = 0; t < 3; t++)
        wmma::store_matrix_sync(Out + t * 16 * ldo + n0, c[t], ldo, wmma::mem_row_major);
}

// ---------------------------------------------------------------------------
// Kernel 1: node message MLP + masked k-sum + residual + LN1 -> g_v1
// One CTA per (b,l). smem: X[48][392], H[48][136]
// ---------------------------------------------------------------------------
__global__ __launch_bounds__(256, 2) void node_kernel(
    const float* __restrict__ hV, const float* __restrict__ hE,
    const int* __restrict__ Eidx, const float* __restrict__ mAtt,
    const float* __restrict__ b1, const float* __restrict__ b2v, const float* __restrict__ b3,
    const float* __restrict__ g1, const float* __restrict__ lb1){
    extern __shared__ __align__(128) float sm[];
    float* Xs = sm;              // 48 x 392
    float* Hs = sm + 48 * 392;   // 48 x 136
    __shared__ float smask[KK];
    __shared__ float red[2][8];
    __shared__ float bc[2];

    int node  = blockIdx.x;
    int baseb = node & ~(LL - 1);
    int tid = threadIdx.x, wid = tid >> 5;
    const float* hVrow = hV + (size_t)node * HH;
    const int*   idxr  = Eidx + (size_t)node * KK;

    for (int i = tid; i < KK * 384; i += 256){
        int r = i / 384, c = i - r * 384;
        float v;
        if      (c < 128) v = hVrow[c];
        else if (c < 256) v = hE[((size_t)node * KK + r) * HH + (c - 128)];
        else              v = hV[((size_t)(baseb + idxr[r])) * HH + (c - 256)];
        Xs[r * 392 + c] = tf32r(v);
    }
    if (tid < KK) smask[tid] = mAtt[(size_t)node * KK + tid];
    __syncthreads();

    int n0 = wid * 16;
    warp_gemm48<48>(Xs, 392, g_cw + CW1, 384, Hs, 136, n0);
    __syncthreads();
    for (int i = tid; i < KK * 128; i += 256){
        int r = i >> 7, c = i & 127;
        Hs[r * 136 + c] = tf32r(gelu_f(Hs[r * 136 + c] + b1[c]));
    }
    __syncthreads();
    warp_gemm48<16>(Hs, 136, g_cw + CW2, 128, Xs, 136, n0);
    __syncthreads();
    for (int i = tid; i < KK * 128; i += 256){
        int r = i >> 7, c = i & 127;
        Xs[r * 136 + c] = tf32r(gelu_f(Xs[r * 136 + c] + b2v[c]));
    }
    __syncthreads();
    warp_gemm48<16>(Xs, 136, g_cw + CW3, 128, Hs, 136, n0);
    __syncthreads();

    float t = 0.f;
    if (tid < 128){
        float b3c = b3[tid], s = 0.f;
#pragma unroll 8
        for (int r = 0; r < KK; r++)
            s += smask[r] * (Hs[r * 136 + tid] + b3c);
        t = hVrow[tid] + s * (1.0f / 30.0f);
    }
    float s1 = t, s2 = t * t;
#pragma unroll
    for (int o = 16; o; o >>= 1){
        s1 += __shfl_xor_sync(0xffffffffu, s1, o);
        s2 += __shfl_xor_sync(0xffffffffu, s2, o);
    }
    if ((tid & 31) == 0){ red[0][wid] = s1; red[1][wid] = s2; }
    __syncthreads();
    if (tid == 0){
        float a = 0.f, q = 0.f;
        for (int i = 0; i < 8; i++){ a += red[0][i]; q += red[1][i]; }
        float m = a * (1.f / 128.f);
        bc[0] = m;
        bc[1] = rsqrtf(q * (1.f / 128.f) - m * m + 1e-5f);
    }
    __syncthreads();
    if (tid < 128)
        g_v1[(size_t)node * HH + tid] = (t - bc[0]) * bc[1] * g1[tid] + lb1[tid];
}

// ---------------------------------------------------------------------------
// Kernel 2: position-wise FFN + residual + LN2 + mask_V -> g_v2 and out h_V
// 64 nodes per CTA. FF=512 processed in 4 chunks of 128 (out acc in registers).
// ---------------------------------------------------------------------------
__global__ __launch_bounds__(256, 2) void ffn_kernel(
    const float* __restrict__ maskV,
    const float* __restrict__ winb, const float* __restrict__ woutb,
    const float* __restrict__ g2, const float* __restrict__ lb2,
    float* __restrict__ outV){
    extern __shared__ __align__(128) float sm[];
    float* Xv = sm;              // 64 x 136
    float* Hc = sm + 64 * 136;   // 64 x 136
    int tid = threadIdx.x, wid = tid >> 5, lane = tid & 31;
    int node0 = blockIdx.x * 64;

    for (int i = tid; i < 64 * 128; i += 256){
        int r = i >> 7, c = i & 127;
        Xv[r * 136 + c] = tf32r(g_v1[(size_t)(node0 + r) * HH + c]);
    }
    __syncthreads();

    int mt = wid & 3, ng = wid >> 2;
    int m0 = mt * 16;
    wmma::fragment<wmma::accumulator,16,16,8,float> accO[4];
#pragma unroll
    for (int j = 0; j < 4; j++) wmma::fill_fragment(accO[j], 0.0f);

    for (int ch = 0; ch < 4; ch++){
        // Hc = gelu(Xv * Win_chunk^T)
#pragma unroll
        for (int j = 0; j < 4; j++){
            int n0 = (ng * 4 + j) * 16;
            wmma::fragment<wmma::accumulator,16,16,8,float> c;
            wmma::fill_fragment(c, 0.0f);
            const float* Bp = g_cw + CWIN + ch * 128 * 128 + n0 * 128;
            wmma::fragment<wmma::matrix_b,16,16,8,wmma::precision::tf32,wmma::col_major> bf[2];
            wmma::load_matrix_sync(bf[0], Bp, 128);
#pragma unroll
            for (int ks = 0; ks < 16; ks++){
                if (ks + 1 < 16) wmma::load_matrix_sync(bf[(ks + 1) & 1], Bp + (ks + 1) * 8, 128);
                wmma::fragment<wmma::matrix_a,16,16,8,wmma::precision::tf32,wmma::row_major> af;
                wmma::load_matrix_sync(af, Xv + m0 * 136 + ks * 8, 136);
                wmma::mma_sync(c, af, bf[ks & 1], c);
            }
            wmma::store_matrix_sync(Hc + m0 * 136 + n0, c, 136, wmma::mem_row_major);
        }
        __syncthreads();
        for (int i = tid; i < 64 * 128; i += 256){
            int r = i >> 7, c = i & 127;
            Hc[r * 136 + c] = tf32r(gelu_f(Hc[r * 136 + c] + winb[ch * 128 + c]));
        }
        __syncthreads();
        // accO += Hc * Wout_chunk^T
#pragma unroll
        for (int j = 0; j < 4; j++){
            int n0g = (ng * 4 + j) * 16;
            const float* Bp = g_cw + CWOUT + n0g * 512 + ch * 128;
            wmma::fragment<wmma::matrix_b,16,16,8,wmma::precision::tf32,wmma::col_major> bf[2];
            wmma::load_matrix_sync(bf[0], Bp, 512);
#pragma unroll
            for (int ks = 0; ks < 16; ks++){
                if (ks + 1 < 16) wmma::load_matrix_sync(bf[(ks + 1) & 1], Bp + (ks + 1) * 8, 512);
                wmma::fragment<wmma::matrix_a,16,16,8,wmma::precision::tf32,wmma::row_major> af;
                wmma::load_matrix_sync(af, Hc + m0 * 136 + ks * 8, 136);
                wmma::mma_sync(accO[j], af, bf[ks & 1], accO[j]);
            }
        }
        __syncthreads();
    }
#pragma unroll
    for (int j = 0; j < 4; j++)
        wmma::store_matrix_sync(Xv + m0 * 136 + (ng * 4 + j) * 16, accO[j], 136, wmma::mem_row_major);
    __syncthreads();

    // per-row LN2 (+ residual from exact fp32 g_v1) then mask_V
    for (int rr = 0; rr < 8; rr++){
        int r = wid * 8 + rr;
        int node = node0 + r;
        float mv = maskV[node];
        float v[4]; float s1 = 0.f, s2 = 0.f;
#pragma unroll
        for (int j = 0; j < 4; j++){
            int c = lane + j * 32;
            float x = g_v1[(size_t)node * HH + c] + Xv[r * 136 + c] + woutb[c];
            v[j] = x; s1 += x; s2 += x * x;
        }
#pragma unroll
        for (int o = 16; o; o >>= 1){
            s1 += __shfl_xor_sync(0xffffffffu, s1, o);
            s2 += __shfl_xor_sync(0xffffffffu, s2, o);
        }
        float m  = s1 * (1.f / 128.f);
        float rs = rsqrtf(s2 * (1.f / 128.f) - m * m + 1e-5f);
#pragma unroll
        for (int j = 0; j < 4; j++){
            int c = lane + j * 32;
            float o = mv * ((v[j] - m) * rs * g2[c] + lb2[c]);
            outV[(size_t)node * HH + c] = o;
            g_v2[(size_t)node * HH + c] = o;
        }
    }
}

// ---------------------------------------------------------------------------
// Kernel 3: edge message MLP + residual + LN3 -> out h_E
// One CTA per (b,l). Same GEMM structure as node_kernel, per-row LN at the end.
// ---------------------------------------------------------------------------
__global__ __launch_bounds__(256, 2) void edge_kernel(
    const float* __restrict__ hE, const int* __restrict__ Eidx,
    const float* __restrict__ b11, const float* __restrict__ b12, const float* __restrict__ b13,
    const float* __restrict__ g3, const float* __restrict__ lb3,
    float* __restrict__ outE){
    extern __shared__ __align__(128) float sm[];
    float* Xs = sm;
    float* Hs = sm + 48 * 392;
    int node  = blockIdx.x;
    int baseb = node & ~(LL - 1);
    int tid = threadIdx.x, wid = tid >> 5, lane = tid & 31;
    const float* vrow = g_v2 + (size_t)node * HH;
    const int*   idxr = Eidx + (size_t)node * KK;

    for (int i = tid; i < KK * 384; i += 256){
        int r = i / 384, c = i - r * 384;
        float v;
        if      (c < 128) v = vrow[c];
        else if (c < 256) v = hE[((size_t)node * KK + r) * HH + (c - 128)];
        else              v = g_v2[((size_t)(baseb + idxr[r])) * HH + (c - 256)];
        Xs[r * 392 + c] = tf32r(v);
    }
    __syncthreads();

    int n0 = wid * 16;
    warp_gemm48<48>(Xs, 392, g_cw + CW11, 384, Hs, 136, n0);
    __syncthreads();
    for (int i = tid; i < KK * 128; i += 256){
        int r = i >> 7, c = i & 127;
        Hs[r * 136 + c] = tf32r(gelu_f(Hs[r * 136 + c] + b11[c]));
    }
    __syncthreads();
    warp_gemm48<16>(Hs, 136, g_cw + CW12, 128, Xs, 136, n0);
    __syncthreads();
    for (int i = tid; i < KK * 128; i += 256){
        int r = i >> 7, c = i & 127;
        Xs[r * 136 + c] = tf32r(gelu_f(Xs[r * 136 + c] + b12[c]));
    }
    __syncthreads();
    warp_gemm48<16>(Xs, 136, g_cw + CW13, 128, Hs, 136, n0);
    __syncthreads();

    // per-row residual + LN3, 6 rows per warp
    for (int rr = 0; rr < 6; rr++){
        int r = wid * 6 + rr;
        const float* her = hE + ((size_t)node * KK + r) * HH;
        float v[4]; float s1 = 0.f, s2 = 0.f;
#pragma unroll
        for (int j = 0; j < 4; j++){
            int c = lane + j * 32;
            float x = her[c] + Hs[r * 136 + c] + b13[c];
            v[j] = x; s1 += x; s2 += x * x;
        }
#pragma unroll
        for (int o = 16; o; o >>= 1){
            s1 += __shfl_xor_sync(0xffffffffu, s1, o);
            s2 += __shfl_xor_sync(0xffffffffu, s2, o);
        }
        float m  = s1 * (1.f / 128.f);
        float rs = rsqrtf(s2 * (1.f / 128.f) - m * m + 1e-5f);
#pragma unroll
        for (int j = 0; j < 4; j++){
            int c = lane + j * 32;
            outE[((size_t)node * KK + r) * HH + c] = (v[j] - m) * rs * g3[c] + lb3[c];
        }
    }
}

// ---------------------------------------------------------------------------
extern "C" void kernel_launch(void* const* d_in, const int* in_sizes, int n_in,
                              void* d_out, int out_size){
    (void)in_sizes; (void)n_in; (void)out_size;
    const float* hV    = (const float*)d_in[0];
    const float* hE    = (const float*)d_in[1];
    const int*   Eidx  = (const int*)  d_in[2];
    const float* maskV = (const float*)d_in[3];
    const float* mAtt  = (const float*)d_in[4];
    const float* W1  = (const float*)d_in[5];  const float* b1  = (const float*)d_in[6];
    const float* W2  = (const float*)d_in[7];  const float* b2  = (const float*)d_in[8];
    const float* W3  = (const float*)d_in[9];  const float* b3  = (const float*)d_in[10];
    const float* W11 = (const float*)d_in[11]; const float* b11 = (const float*)d_in[12];
    const float* W12 = (const float*)d_in[13]; const float* b12 = (const float*)d_in[14];
    const float* W13 = (const float*)d_in[15]; const float* b13 = (const float*)d_in[16];
    const float* Win = (const float*)d_in[17]; const float* Winb = (const float*)d_in[18];
    const float* Wout= (const float*)d_in[19]; const float* Woutb= (const float*)d_in[20];
    const float* g1  = (const float*)d_in[21]; const float* lb1 = (const float*)d_in[22];
    const float* g2  = (const float*)d_in[23]; const float* lb2 = (const float*)d_in[24];
    const float* g3  = (const float*)d_in[25]; const float* lb3 = (const float*)d_in[26];

    float* outV = (float*)d_out;
    float* outE = outV + (size_t)BB * LL * HH;

    const int smem1 = (48 * 392 + 48 * 136) * 4;   // 101,376 B
    const int smem2 = 2 * 64 * 136 * 4;            //  69,632 B
    cudaFuncSetAttribute(node_kernel, cudaFuncAttributeMaxDynamicSharedMemorySize, smem1);
    cudaFuncSetAttribute(edge_kernel, cudaFuncAttributeMaxDynamicSharedMemorySize, smem1);
    cudaFuncSetAttribute(ffn_kernel,  cudaFuncAttributeMaxDynamicSharedMemorySize, smem2);

    cvt_weights<<<(CWTOT + 255) / 256, 256>>>(W1, W2, W3, W11, W12, W13, Win, Wout);
    node_kernel<<<BB * LL, 256, smem1>>>(hV, hE, Eidx, mAtt, b1, b2, b3, g1, lb1);
    ffn_kernel<<<BB * LL / 64, 256, smem2>>>(maskV, Winb, Woutb, g2, lb2, outV);
    edge_kernel<<<BB * LL, 256, smem1>>>(hE, Eidx, b11, b12, b13, g3, lb3, outE);
}

// round 10
// speedup vs baseline: 1.4647x; 1.4647x over previous
#include <cuda_runtime.h>
#include <cuda_bf16.h>
#include <mma.h>
#include <math.h>

using namespace nvcuda;

#define BB 4
#define LL 2048
#define KK 48
#define HH 128
#define FFD 512

// bf16 weights (node + edge MLPs)
#define NB1   0
#define NB2   49152
#define NB3   65536
#define NB11  81920
#define NB12  131072
#define NB13  147456
#define NBTOT 163840
// tf32-f32 weights (FFN)
#define CWIN  0
#define CWOUT 65536
#define CWTOT 131072

__device__ __nv_bfloat16 g_wb[NBTOT];
__device__ float g_cw[CWTOT];
__device__ float g_v1[BB*LL*HH];   // h_V after node update + LN1
__device__ float g_v2[BB*LL*HH];   // h_V after FFN + LN2 + mask

#define XLD 392   // bf16 X tile row stride (elements)
#define FLD 132   // f32 staging row stride
#define HLD 136   // bf16 H tile row stride
#define XBYTES (96*XLD*2)   // 75264

__device__ __forceinline__ float tf32r(float x){
    float r;
    asm("{\n .reg .b32 t;\n cvt.rna.tf32.f32 t, %1;\n mov.b32 %0, t;\n}"
        : "=f"(r) : "f"(x));
    return r;
}
__device__ __forceinline__ float gelu_f(float x){
    return 0.5f * x * (1.0f + erff(x * 0.7071067811865476f));
}

// ---------------------------------------------------------------------------
// Weight conversion: MLP weights -> bf16, FFN weights -> tf32-rounded f32
// ---------------------------------------------------------------------------
__global__ void cvt_weights(const float* __restrict__ w1, const float* __restrict__ w2,
                            const float* __restrict__ w3, const float* __restrict__ w11,
                            const float* __restrict__ w12, const float* __restrict__ w13,
                            const float* __restrict__ win, const float* __restrict__ wout){
    int i = blockIdx.x * blockDim.x + threadIdx.x;
    if (i < NBTOT){
        float v;
        if      (i < NB2)   v = w1[i - NB1];
        else if (i < NB3)   v = w2[i - NB2];
        else if (i < NB11)  v = w3[i - NB3];
        else if (i < NB12)  v = w11[i - NB11];
        else if (i < NB13)  v = w12[i - NB12];
        else                v = w13[i - NB13];
        g_wb[i] = __float2bfloat16(v);
    }
    if (i < CWTOT){
        float w = (i < CWOUT) ? win[i] : wout[i - CWOUT];
        g_cw[i] = tf32r(w);
    }
}

// ---------------------------------------------------------------------------
// Warp GEMM on a 96-row tile: warp (mw in 0..1, nw in 0..3) computes the
// 48x32 block (3 m-tiles x 2 n-tiles), f32 acc kept in registers by caller.
// A: smem bf16 row-major (lda=XLD or HLD); B: global bf16 "W" row-major
// viewed as col_major with ldb = K.
// ---------------------------------------------------------------------------
using FragA = wmma::fragment<wmma::matrix_a,16,16,16,__nv_bfloat16,wmma::row_major>;
using FragB = wmma::fragment<wmma::matrix_b,16,16,16,__nv_bfloat16,wmma::col_major>;
using FragC = wmma::fragment<wmma::accumulator,16,16,16,float>;

template<int NK>
__device__ __forceinline__ void wg96(const __nv_bfloat16* __restrict__ As, int lda,
                                     const __nv_bfloat16* __restrict__ Bg, int ldb,
                                     FragC (&acc)[3][2], int mw, int nw){
#pragma unroll
    for (int t = 0; t < 3; t++)
#pragma unroll
        for (int u = 0; u < 2; u++) wmma::fill_fragment(acc[t][u], 0.0f);

    const __nv_bfloat16* B0 = Bg + (size_t)(nw * 32) * ldb;
    const __nv_bfloat16* B1 = B0 + (size_t)16 * ldb;
    const __nv_bfloat16* Am = As + (size_t)(mw * 48) * lda;

    FragB bf[2][2];
    wmma::load_matrix_sync(bf[0][0], B0, ldb);
    wmma::load_matrix_sync(bf[0][1], B1, ldb);
#pragma unroll 4
    for (int ks = 0; ks < NK; ks++){
        if (ks + 1 < NK){
            wmma::load_matrix_sync(bf[(ks + 1) & 1][0], B0 + (ks + 1) * 16, ldb);
            wmma::load_matrix_sync(bf[(ks + 1) & 1][1], B1 + (ks + 1) * 16, ldb);
        }
#pragma unroll
        for (int t = 0; t < 3; t++){
            FragA af;
            wmma::load_matrix_sync(af, Am + t * 16 * lda + ks * 16, lda);
            wmma::mma_sync(acc[t][0], af, bf[ks & 1][0], acc[t][0]);
            wmma::mma_sync(acc[t][1], af, bf[ks & 1][1], acc[t][1]);
        }
    }
}

__device__ __forceinline__ void store_acc(FragC (&acc)[3][2], float* F, int mw, int nw){
#pragma unroll
    for (int t = 0; t < 3; t++)
#pragma unroll
        for (int u = 0; u < 2; u++)
            wmma::store_matrix_sync(F + (size_t)(mw * 48 + t * 16) * FLD + nw * 32 + u * 16,
                                    acc[t][u], FLD, wmma::mem_row_major);
}

// ---------------------------------------------------------------------------
// Kernel 1: node message MLP + masked k-sum + residual + LN1 -> g_v1
// 2 nodes per CTA (96 rows). smem: bfX[96][392] (aliased with f32 F[96][132]),
// bfH[96][136].
// ---------------------------------------------------------------------------
__global__ __launch_bounds__(256, 2) void node_kernel(
    const float* __restrict__ hV, const float* __restrict__ hE,
    const int* __restrict__ Eidx, const float* __restrict__ mAtt,
    const float* __restrict__ b1, const float* __restrict__ b2v, const float* __restrict__ b3,
    const float* __restrict__ g1, const float* __restrict__ lb1){
    extern __shared__ __align__(128) char smc[];
    __nv_bfloat16* bfX = (__nv_bfloat16*)smc;
    float*         F   = (float*)smc;
    __nv_bfloat16* bfH = (__nv_bfloat16*)(smc + XBYTES);
    __shared__ float smask[96];
    __shared__ float red[2][8];
    __shared__ float bc[2][2];

    int nA  = blockIdx.x * 2;
    int tid = threadIdx.x, wid = tid >> 5;
    int mw = wid >> 2, nw = wid & 3;

    // build concat tile [96 x 384] in bf16
    for (int i = tid; i < 96 * 384; i += 256){
        int r = i / 384, c = i - r * 384;
        int half = (r >= 48);
        int node = nA + half;
        int rr = r - half * 48;
        float v;
        if      (c < 128) v = hV[(size_t)node * HH + c];
        else if (c < 256) v = hE[((size_t)node * KK + rr) * HH + (c - 128)];
        else{
            int baseb = node & ~(LL - 1);
            int idx = Eidx[(size_t)node * KK + rr];
            v = hV[((size_t)(baseb + idx)) * HH + (c - 256)];
        }
        bfX[(size_t)r * XLD + c] = __float2bfloat16(v);
    }
    if (tid < 96) smask[tid] = mAtt[(size_t)nA * KK + tid];
    __syncthreads();

    FragC acc[3][2];
    // layer 1: [96x384] x [384x128]
    wg96<24>(bfX, XLD, g_wb + NB1, 384, acc, mw, nw);
    __syncthreads();                 // all warps done reading bfX
    store_acc(acc, F, mw, nw);       // overwrite aliased region
    __syncthreads();
    for (int i = tid; i < 96 * 128; i += 256){
        int r = i >> 7, c = i & 127;
        bfH[r * HLD + c] = __float2bfloat16(gelu_f(F[r * FLD + c] + b1[c]));
    }
    __syncthreads();
    // layer 2
    wg96<8>(bfH, HLD, g_wb + NB2, 128, acc, mw, nw);
    __syncthreads();
    store_acc(acc, F, mw, nw);
    __syncthreads();
    for (int i = tid; i < 96 * 128; i += 256){
        int r = i >> 7, c = i & 127;
        bfH[r * HLD + c] = __float2bfloat16(gelu_f(F[r * FLD + c] + b2v[c]));
    }
    __syncthreads();
    // layer 3
    wg96<8>(bfH, HLD, g_wb + NB3, 128, acc, mw, nw);
    __syncthreads();
    store_acc(acc, F, mw, nw);
    __syncthreads();

    // masked k-sum /30 + residual, per-node LN over 128 channels
    int j = tid >> 7, col = tid & 127;
    int node = nA + j;
    float b3c = b3[col], s = 0.f;
#pragma unroll 8
    for (int r = 0; r < KK; r++)
        s += smask[j * KK + r] * (F[(j * KK + r) * FLD + col] + b3c);
    float t = hV[(size_t)node * HH + col] + s * (1.0f / 30.0f);

    float s1 = t, s2 = t * t;
#pragma unroll
    for (int o = 16; o; o >>= 1){
        s1 += __shfl_xor_sync(0xffffffffu, s1, o);
        s2 += __shfl_xor_sync(0xffffffffu, s2, o);
    }
    if ((tid & 31) == 0){ red[0][wid] = s1; red[1][wid] = s2; }
    __syncthreads();
    if (tid < 2){
        float a = 0.f, q = 0.f;
        for (int i = 0; i < 4; i++){ a += red[0][tid * 4 + i]; q += red[1][tid * 4 + i]; }
        float m = a * (1.f / 128.f);
        bc[tid][0] = m;
        bc[tid][1] = rsqrtf(q * (1.f / 128.f) - m * m + 1e-5f);
    }
    __syncthreads();
    g_v1[(size_t)node * HH + col] = (t - bc[j][0]) * bc[j][1] * g1[col] + lb1[col];
}

// ---------------------------------------------------------------------------
// Kernel 2: position-wise FFN + residual + LN2 + mask_V -> g_v2 and out h_V
// (tf32 path, unchanged from R7)
// ---------------------------------------------------------------------------
__global__ __launch_bounds__(256, 2) void ffn_kernel(
    const float* __restrict__ maskV,
    const float* __restrict__ winb, const float* __restrict__ woutb,
    const float* __restrict__ g2, const float* __restrict__ lb2,
    float* __restrict__ outV){
    extern __shared__ __align__(128) float sm[];
    float* Xv = sm;              // 64 x 136
    float* Hc = sm + 64 * 136;   // 64 x 136
    int tid = threadIdx.x, wid = tid >> 5, lane = tid & 31;
    int node0 = blockIdx.x * 64;

    for (int i = tid; i < 64 * 128; i += 256){
        int r = i >> 7, c = i & 127;
        Xv[r * 136 + c] = tf32r(g_v1[(size_t)(node0 + r) * HH + c]);
    }
    __syncthreads();

    int mt = wid & 3, ng = wid >> 2;
    int m0 = mt * 16;
    wmma::fragment<wmma::accumulator,16,16,8,float> accO[4];
#pragma unroll
    for (int j = 0; j < 4; j++) wmma::fill_fragment(accO[j], 0.0f);

    for (int ch = 0; ch < 4; ch++){
#pragma unroll
        for (int j = 0; j < 4; j++){
            int n0 = (ng * 4 + j) * 16;
            wmma::fragment<wmma::accumulator,16,16,8,float> c;
            wmma::fill_fragment(c, 0.0f);
            const float* Bp = g_cw + CWIN + ch * 128 * 128 + n0 * 128;
            wmma::fragment<wmma::matrix_b,16,16,8,wmma::precision::tf32,wmma::col_major> bf[2];
            wmma::load_matrix_sync(bf[0], Bp, 128);
#pragma unroll
            for (int ks = 0; ks < 16; ks++){
                if (ks + 1 < 16) wmma::load_matrix_sync(bf[(ks + 1) & 1], Bp + (ks + 1) * 8, 128);
                wmma::fragment<wmma::matrix_a,16,16,8,wmma::precision::tf32,wmma::row_major> af;
                wmma::load_matrix_sync(af, Xv + m0 * 136 + ks * 8, 136);
                wmma::mma_sync(c, af, bf[ks & 1], c);
            }
            wmma::store_matrix_sync(Hc + m0 * 136 + n0, c, 136, wmma::mem_row_major);
        }
        __syncthreads();
        for (int i = tid; i < 64 * 128; i += 256){
            int r = i >> 7, c = i & 127;
            Hc[r * 136 + c] = tf32r(gelu_f(Hc[r * 136 + c] + winb[ch * 128 + c]));
        }
        __syncthreads();
#pragma unroll
        for (int j = 0; j < 4; j++){
            int n0g = (ng * 4 + j) * 16;
            const float* Bp = g_cw + CWOUT + n0g * 512 + ch * 128;
            wmma::fragment<wmma::matrix_b,16,16,8,wmma::precision::tf32,wmma::col_major> bf[2];
            wmma::load_matrix_sync(bf[0], Bp, 512);
#pragma unroll
            for (int ks = 0; ks < 16; ks++){
                if (ks + 1 < 16) wmma::load_matrix_sync(bf[(ks + 1) & 1], Bp + (ks + 1) * 8, 512);
                wmma::fragment<wmma::matrix_a,16,16,8,wmma::precision::tf32,wmma::row_major> af;
                wmma::load_matrix_sync(af, Hc + m0 * 136 + ks * 8, 136);
                wmma::mma_sync(accO[j], af, bf[ks & 1], accO[j]);
            }
        }
        __syncthreads();
    }
#pragma unroll
    for (int j = 0; j < 4; j++)
        wmma::store_matrix_sync(Xv + m0 * 136 + (ng * 4 + j) * 16, accO[j], 136, wmma::mem_row_major);
    __syncthreads();

    for (int rr = 0; rr < 8; rr++){
        int r = wid * 8 + rr;
        int node = node0 + r;
        float mv = maskV[node];
        float v[4]; float s1 = 0.f, s2 = 0.f;
#pragma unroll
        for (int j = 0; j < 4; j++){
            int c = lane + j * 32;
            float x = g_v1[(size_t)node * HH + c] + Xv[r * 136 + c] + woutb[c];
            v[j] = x; s1 += x; s2 += x * x;
        }
#pragma unroll
        for (int o = 16; o; o >>= 1){
            s1 += __shfl_xor_sync(0xffffffffu, s1, o);
            s2 += __shfl_xor_sync(0xffffffffu, s2, o);
        }
        float m  = s1 * (1.f / 128.f);
        float rs = rsqrtf(s2 * (1.f / 128.f) - m * m + 1e-5f);
#pragma unroll
        for (int j = 0; j < 4; j++){
            int c = lane + j * 32;
            float o = mv * ((v[j] - m) * rs * g2[c] + lb2[c]);
            outV[(size_t)node * HH + c] = o;
            g_v2[(size_t)node * HH + c] = o;
        }
    }
}

// ---------------------------------------------------------------------------
// Kernel 3: edge message MLP + residual + LN3 -> out h_E (2 nodes per CTA)
// ---------------------------------------------------------------------------
__global__ __launch_bounds__(256, 2) void edge_kernel(
    const float* __restrict__ hE, const int* __restrict__ Eidx,
    const float* __restrict__ b11, const float* __restrict__ b12, const float* __restrict__ b13,
    const float* __restrict__ g3, const float* __restrict__ lb3,
    float* __restrict__ outE){
    extern __shared__ __align__(128) char smc[];
    __nv_bfloat16* bfX = (__nv_bfloat16*)smc;
    float*         F   = (float*)smc;
    __nv_bfloat16* bfH = (__nv_bfloat16*)(smc + XBYTES);

    int nA  = blockIdx.x * 2;
    int tid = threadIdx.x, wid = tid >> 5, lane = tid & 31;
    int mw = wid >> 2, nw = wid & 3;

    for (int i = tid; i < 96 * 384; i += 256){
        int r = i / 384, c = i - r * 384;
        int half = (r >= 48);
        int node = nA + half;
        int rr = r - half * 48;
        float v;
        if      (c < 128) v = g_v2[(size_t)node * HH + c];
        else if (c < 256) v = hE[((size_t)node * KK + rr) * HH + (c - 128)];
        else{
            int baseb = node & ~(LL - 1);
            int idx = Eidx[(size_t)node * KK + rr];
            v = g_v2[((size_t)(baseb + idx)) * HH + (c - 256)];
        }
        bfX[(size_t)r * XLD + c] = __float2bfloat16(v);
    }
    __syncthreads();

    FragC acc[3][2];
    wg96<24>(bfX, XLD, g_wb + NB11, 384, acc, mw, nw);
    __syncthreads();
    store_acc(acc, F, mw, nw);
    __syncthreads();
    for (int i = tid; i < 96 * 128; i += 256){
        int r = i >> 7, c = i & 127;
        bfH[r * HLD + c] = __float2bfloat16(gelu_f(F[r * FLD + c] + b11[c]));
    }
    __syncthreads();
    wg96<8>(bfH, HLD, g_wb + NB12, 128, acc, mw, nw);
    __syncthreads();
    store_acc(acc, F, mw, nw);
    __syncthreads();
    for (int i = tid; i < 96 * 128; i += 256){
        int r = i >> 7, c = i & 127;
        bfH[r * HLD + c] = __float2bfloat16(gelu_f(F[r * FLD + c] + b12[c]));
    }
    __syncthreads();
    wg96<8>(bfH, HLD, g_wb + NB13, 128, acc, mw, nw);
    __syncthreads();
    store_acc(acc, F, mw, nw);
    __syncthreads();

    // per-row residual + LN3: 12 rows per warp
    for (int rr = 0; rr < 12; rr++){
        int r = wid * 12 + rr;
        int half = (r >= 48);
        int node = nA + half;
        int er = r - half * 48;
        const float* her = hE + ((size_t)node * KK + er) * HH;
        float v[4]; float s1 = 0.f, s2 = 0.f;
#pragma unroll
        for (int j = 0; j < 4; j++){
            int c = lane + j * 32;
            float x = her[c] + F[r * FLD + c] + b13[c];
            v[j] = x; s1 += x; s2 += x * x;
        }
#pragma unroll
        for (int o = 16; o; o >>= 1){
            s1 += __shfl_xor_sync(0xffffffffu, s1, o);
            s2 += __shfl_xor_sync(0xffffffffu, s2, o);
        }
        float m  = s1 * (1.f / 128.f);
        float rs = rsqrtf(s2 * (1.f / 128.f) - m * m + 1e-5f);
#pragma unroll
        for (int j = 0; j < 4; j++){
            int c = lane + j * 32;
            outE[((size_t)node * KK + er) * HH + c] = (v[j] - m) * rs * g3[c] + lb3[c];
        }
    }
}

// ---------------------------------------------------------------------------
extern "C" void kernel_launch(void* const* d_in, const int* in_sizes, int n_in,
                              void* d_out, int out_size){
    (void)in_sizes; (void)n_in; (void)out_size;
    const float* hV    = (const float*)d_in[0];
    const float* hE    = (const float*)d_in[1];
    const int*   Eidx  = (const int*)  d_in[2];
    const float* maskV = (const float*)d_in[3];
    const float* mAtt  = (const float*)d_in[4];
    const float* W1  = (const float*)d_in[5];  const float* b1  = (const float*)d_in[6];
    const float* W2  = (const float*)d_in[7];  const float* b2  = (const float*)d_in[8];
    const float* W3  = (const float*)d_in[9];  const float* b3  = (const float*)d_in[10];
    const float* W11 = (const float*)d_in[11]; const float* b11 = (const float*)d_in[12];
    const float* W12 = (const float*)d_in[13]; const float* b12 = (const float*)d_in[14];
    const float* W13 = (const float*)d_in[15]; const float* b13 = (const float*)d_in[16];
    const float* Win = (const float*)d_in[17]; const float* Winb = (const float*)d_in[18];
    const float* Wout= (const float*)d_in[19]; const float* Woutb= (const float*)d_in[20];
    const float* g1  = (const float*)d_in[21]; const float* lb1 = (const float*)d_in[22];
    const float* g2  = (const float*)d_in[23]; const float* lb2 = (const float*)d_in[24];
    const float* g3  = (const float*)d_in[25]; const float* lb3 = (const float*)d_in[26];

    float* outV = (float*)d_out;
    float* outE = outV + (size_t)BB * LL * HH;

    const int smem1 = XBYTES + 96 * HLD * 2;       // 75264 + 26112 = 101376 B
    const int smem2 = 2 * 64 * 136 * 4;            // 69632 B
    cudaFuncSetAttribute(node_kernel, cudaFuncAttributeMaxDynamicSharedMemorySize, smem1);
    cudaFuncSetAttribute(edge_kernel, cudaFuncAttributeMaxDynamicSharedMemorySize, smem1);
    cudaFuncSetAttribute(ffn_kernel,  cudaFuncAttributeMaxDynamicSharedMemorySize, smem2);

    cvt_weights<<<(NBTOT + 255) / 256, 256>>>(W1, W2, W3, W11, W12, W13, Win, Wout);
    node_kernel<<<BB * LL / 2, 256, smem1>>>(hV, hE, Eidx, mAtt, b1, b2, b3, g1, lb1);
    ffn_kernel<<<BB * LL / 64, 256, smem2>>>(maskV, Winb, Woutb, g2, lb2, outV);
    edge_kernel<<<BB * LL / 2, 256, smem1>>>(hE, Eidx, b11, b12, b13, g3, lb3, outE);
}